// round 1
// baseline (speedup 1.0000x reference)
#include <cuda_runtime.h>
#include <cuda_bf16.h>

#define SEQ   2048
#define DIN   2048
#define NH    32
#define NKV   8
#define HD    128
#define QDIM  (NH * HD)    // 4096
#define KVDIM (NKV * HD)   // 1024

#define BM 128
#define BN 128
#define BK 16
#define TM 8
#define TN 8

// ---------------- static scratch (no allocations allowed) ----------------
__device__ float g_Q[(size_t)SEQ * QDIM];                 // 32 MB
__device__ float g_Kp[(size_t)SEQ * KVDIM];               // 8 MB
__device__ float g_Vp[(size_t)SEQ * KVDIM];               // 8 MB
__device__ float g_ctx[(size_t)SEQ * QDIM];               // 32 MB
__device__ float g_S[(size_t)NH * SEQ * SEQ];             // 512 MB

// ---------------- generic NN GEMM body --------------------------------
// A: pre-offset to tile row, lda row stride
// B: pre-offset to tile col, ldb row stride
// C: pre-offset to tile origin, ldc row stride
__device__ __forceinline__ void gemm_nn_body(
    const float* __restrict__ A, const float* __restrict__ B, float* __restrict__ C,
    int lda, int ldb, int ldc, int K,
    float (*As)[BM], float (*Bs)[BN])
{
    int tid = threadIdx.x;
    int tr = (tid >> 4) * TM;
    int tc = (tid & 15) * TN;

    float acc[TM][TN];
#pragma unroll
    for (int i = 0; i < TM; i++)
#pragma unroll
        for (int j = 0; j < TN; j++) acc[i][j] = 0.f;

    for (int k0 = 0; k0 < K; k0 += BK) {
        // A tile: BM x BK, store transposed As[k][m]
#pragma unroll
        for (int i = 0; i < 2; i++) {
            int f  = tid + i * 256;
            int r  = f >> 2;
            int kq = (f & 3) << 2;
            float4 v = *(const float4*)(A + (size_t)r * lda + k0 + kq);
            As[kq + 0][r] = v.x; As[kq + 1][r] = v.y;
            As[kq + 2][r] = v.z; As[kq + 3][r] = v.w;
        }
        // B tile: BK x BN, direct
#pragma unroll
        for (int i = 0; i < 2; i++) {
            int f = tid + i * 256;
            int r = f >> 5;
            int c = (f & 31) << 2;
            *(float4*)&Bs[r][c] = *(const float4*)(B + (size_t)(k0 + r) * ldb + c);
        }
        __syncthreads();
#pragma unroll
        for (int kk = 0; kk < BK; kk++) {
            float a[TM], b[TN];
#pragma unroll
            for (int i = 0; i < TM; i++) a[i] = As[kk][tr + i];
#pragma unroll
            for (int j = 0; j < TN; j++) b[j] = Bs[kk][tc + j];
#pragma unroll
            for (int i = 0; i < TM; i++)
#pragma unroll
                for (int j = 0; j < TN; j++) acc[i][j] += a[i] * b[j];
        }
        __syncthreads();
    }

#pragma unroll
    for (int i = 0; i < TM; i++)
#pragma unroll
        for (int j = 0; j < TN; j += 4) {
            float4 v = make_float4(acc[i][j], acc[i][j + 1], acc[i][j + 2], acc[i][j + 3]);
            *(float4*)(C + (size_t)(tr + i) * ldc + tc + j) = v;
        }
}

__global__ void __launch_bounds__(256) gemm_nn_kernel(
    const float* __restrict__ A, const float* __restrict__ B, float* __restrict__ C,
    int lda, int ldb, int ldc, int K)
{
    __shared__ float As[BK][BM];
    __shared__ float Bs[BK][BN];
    size_t row0 = (size_t)blockIdx.y * BM;
    size_t col0 = (size_t)blockIdx.x * BN;
    gemm_nn_body(A + row0 * lda, B + col0, C + row0 * ldc + col0,
                 lda, ldb, ldc, K, As, Bs);
}

// S = Q_h @ K_kv^T with causal tile skip
__global__ void __launch_bounds__(256) scores_kernel(
    const float* __restrict__ Q, const float* __restrict__ Kc, float* __restrict__ S)
{
    int h   = blockIdx.z;
    int kv  = h >> 2;          // GROUP = 4
    int row0 = blockIdx.y * BM;   // query tile
    int col0 = blockIdx.x * BN;   // key tile
    if (col0 > row0 + (BM - 1)) return;   // fully masked tile

    __shared__ float As[BK][BM];
    __shared__ float Bs[BK][BN];

    const float* A = Q  + (size_t)row0 * QDIM + (size_t)h * HD;
    const float* B = Kc + (size_t)kv * SEQ * HD + (size_t)col0 * HD;
    float*       C = g_S + (size_t)h * SEQ * SEQ + (size_t)row0 * SEQ + col0;
    (void)S;

    int tid = threadIdx.x;
    int tr = (tid >> 4) * TM;
    int tc = (tid & 15) * TN;
    float acc[TM][TN];
#pragma unroll
    for (int i = 0; i < TM; i++)
#pragma unroll
        for (int j = 0; j < TN; j++) acc[i][j] = 0.f;

    for (int k0 = 0; k0 < HD; k0 += BK) {
#pragma unroll
        for (int i = 0; i < 2; i++) {
            int f  = tid + i * 256;
            int r  = f >> 2;
            int kq = (f & 3) << 2;
            float4 v = *(const float4*)(A + (size_t)r * QDIM + k0 + kq);
            As[kq + 0][r] = v.x; As[kq + 1][r] = v.y;
            As[kq + 2][r] = v.z; As[kq + 3][r] = v.w;
        }
        // B is [n][k] row-major (ldb = HD): Bs[k][n] = B[n*HD + k]
#pragma unroll
        for (int i = 0; i < 2; i++) {
            int f  = tid + i * 256;
            int n  = f >> 2;
            int kq = (f & 3) << 2;
            float4 v = *(const float4*)(B + (size_t)n * HD + k0 + kq);
            Bs[kq + 0][n] = v.x; Bs[kq + 1][n] = v.y;
            Bs[kq + 2][n] = v.z; Bs[kq + 3][n] = v.w;
        }
        __syncthreads();
#pragma unroll
        for (int kk = 0; kk < BK; kk++) {
            float a[TM], b[TN];
#pragma unroll
            for (int i = 0; i < TM; i++) a[i] = As[kk][tr + i];
#pragma unroll
            for (int j = 0; j < TN; j++) b[j] = Bs[kk][tc + j];
#pragma unroll
            for (int i = 0; i < TM; i++)
#pragma unroll
                for (int j = 0; j < TN; j++) acc[i][j] += a[i] * b[j];
        }
        __syncthreads();
    }
#pragma unroll
    for (int i = 0; i < TM; i++)
#pragma unroll
        for (int j = 0; j < TN; j += 4) {
            float4 v = make_float4(acc[i][j], acc[i][j + 1], acc[i][j + 2], acc[i][j + 3]);
            *(float4*)(C + (size_t)(tr + i) * SEQ + tc + j) = v;
        }
}

// ctx_h = P_h @ V_kv   (N = HD = 128, one col tile)
__global__ void __launch_bounds__(256) pv_kernel(
    const float* __restrict__ V, float* __restrict__ ctx)
{
    __shared__ float As[BK][BM];
    __shared__ float Bs[BK][BN];
    int h  = blockIdx.z;
    int kv = h >> 2;
    size_t row0 = (size_t)blockIdx.y * BM;
    const float* A = g_S + (size_t)h * SEQ * SEQ + row0 * SEQ;
    const float* B = V + (size_t)kv * SEQ * HD;
    float*       C = ctx + row0 * QDIM + (size_t)h * HD;
    gemm_nn_body(A, B, C, SEQ, HD, QDIM, SEQ, As, Bs);
}

// ---------------- RMSNorm + RoPE (fused) --------------------------------
__global__ void norm_rope_kernel(
    const float* __restrict__ in, float* __restrict__ out,
    const float* __restrict__ scale,
    const float* __restrict__ cosb, const float* __restrict__ sinb,
    int in_tok_stride, int in_head_stride,
    int out_tok_stride, int out_head_stride)
{
    int t = blockIdx.x, h = blockIdx.y, d = threadIdx.x;
    __shared__ float red[HD];
    __shared__ float sm[HD];

    float val = in[(size_t)t * in_tok_stride + (size_t)h * in_head_stride + d];
    red[d] = val * val;
    __syncthreads();
#pragma unroll
    for (int s = 64; s > 0; s >>= 1) {
        if (d < s) red[d] += red[d + s];
        __syncthreads();
    }
    float rms = rsqrtf(red[0] * (1.0f / HD) + 1e-6f);
    float nv  = val * rms * scale[d];
    sm[d] = nv;
    __syncthreads();
    float partner = (d < 64) ? sm[d + 64] : sm[d - 64];
    float rot     = (d < 64) ? -partner   : partner;
    float o = nv * cosb[t * HD + d] + rot * sinb[t * HD + d];
    out[(size_t)t * out_tok_stride + (size_t)h * out_head_stride + d] = o;
}

// V layout shuffle: [t][kv*128+d] -> [kv][t][d]
__global__ void vcopy_kernel(const float* __restrict__ Vp, float* __restrict__ Vout)
{
    int i = blockIdx.x * blockDim.x + threadIdx.x;
    int t = i >> 10;
    int c = i & 1023;
    int kv = c >> 7;
    int d  = c & 127;
    Vout[((size_t)kv * SEQ + t) * HD + d] = Vp[i];
}

// ---------------- causal softmax over S rows -----------------------------
__global__ void __launch_bounds__(256) softmax_kernel(float* __restrict__ Sg)
{
    int q = blockIdx.x, h = blockIdx.y;
    float* row = Sg + (size_t)h * SEQ * SEQ + (size_t)q * SEQ;
    int len = q + 1;
    const float scl = 0.08838834764831845f;   // 1/sqrt(128)
    __shared__ float red[256];
    int tid = threadIdx.x;

    float m = -1e30f;
    for (int i = tid; i < len; i += 256) m = fmaxf(m, row[i]);
    red[tid] = m;
    __syncthreads();
#pragma unroll
    for (int s = 128; s > 0; s >>= 1) {
        if (tid < s) red[tid] = fmaxf(red[tid], red[tid + s]);
        __syncthreads();
    }
    m = red[0] * scl;
    __syncthreads();

    float sum = 0.f;
    for (int i = tid; i < len; i += 256) {
        float e = __expf(row[i] * scl - m);
        row[i] = e;
        sum += e;
    }
    red[tid] = sum;
    __syncthreads();
#pragma unroll
    for (int s = 128; s > 0; s >>= 1) {
        if (tid < s) red[tid] += red[tid + s];
        __syncthreads();
    }
    float inv = 1.f / red[0];
    for (int i = tid; i < len; i += 256)       row[i] *= inv;
    for (int i = len + tid; i < SEQ; i += 256) row[i]  = 0.f;
}

// ---------------- launch -------------------------------------------------
extern "C" void kernel_launch(void* const* d_in, const int* in_sizes, int n_in,
                              void* d_out, int out_size)
{
    const float* x       = (const float*)d_in[0];
    const float* Wq      = (const float*)d_in[1];
    const float* Wk      = (const float*)d_in[2];
    const float* Wv      = (const float*)d_in[3];
    const float* Wo      = (const float*)d_in[4];
    const float* q_scale = (const float*)d_in[5];
    const float* k_scale = (const float*)d_in[6];
    const float* cosb    = (const float*)d_in[7];
    const float* sinb    = (const float*)d_in[8];
    // d_in[9] = mask (causal, recomputed), d_in[10] = start_pos (0)

    float* out  = (float*)d_out;
    float* Kout = out  + (size_t)SEQ * DIN;          // k: [8][2048][128]
    float* Vout = Kout + (size_t)NKV * SEQ * HD;     // v: [8][2048][128]

    float *Q, *Kp, *Vp, *ctx, *S;
    cudaGetSymbolAddress((void**)&Q,   g_Q);
    cudaGetSymbolAddress((void**)&Kp,  g_Kp);
    cudaGetSymbolAddress((void**)&Vp,  g_Vp);
    cudaGetSymbolAddress((void**)&ctx, g_ctx);
    cudaGetSymbolAddress((void**)&S,   g_S);

    dim3 blk(256);

    // projections
    gemm_nn_kernel<<<dim3(QDIM / BN,  SEQ / BM), blk>>>(x, Wq, Q,  DIN, QDIM,  QDIM,  DIN);
    gemm_nn_kernel<<<dim3(KVDIM / BN, SEQ / BM), blk>>>(x, Wk, Kp, DIN, KVDIM, KVDIM, DIN);
    gemm_nn_kernel<<<dim3(KVDIM / BN, SEQ / BM), blk>>>(x, Wv, Vp, DIN, KVDIM, KVDIM, DIN);

    // rmsnorm + rope; K lands directly in the output KV cache layout
    norm_rope_kernel<<<dim3(SEQ, NH),  HD>>>(Q,  Q,    q_scale, cosb, sinb, QDIM,  HD, QDIM, HD);
    norm_rope_kernel<<<dim3(SEQ, NKV), HD>>>(Kp, Kout, k_scale, cosb, sinb, KVDIM, HD, HD,   SEQ * HD);
    vcopy_kernel<<<(SEQ * KVDIM) / 256, 256>>>(Vp, Vout);

    // attention
    scores_kernel<<<dim3(SEQ / BN, SEQ / BM, NH), blk>>>(Q, Kout, S);
    softmax_kernel<<<dim3(SEQ, NH), blk>>>(S);
    pv_kernel<<<dim3(1, SEQ / BM, NH), blk>>>(Vout, ctx);

    // output projection
    gemm_nn_kernel<<<dim3(DIN / BN, SEQ / BM), blk>>>(ctx, Wo, out, QDIM, DIN, DIN, QDIM);
}

// round 3
// speedup vs baseline: 2.5534x; 2.5534x over previous
#include <cuda_runtime.h>
#include <cuda_bf16.h>
#include <cstdint>

#define SEQ 2048
#define DIN 2048
#define NH 32
#define NKV 8
#define HD 128
#define QDIM 4096
#define KVDIM 1024

typedef __nv_bfloat16 bf16;
typedef __nv_bfloat162 bf162;

#define BM 128
#define BN 128
#define BK 32

// ---------------- static scratch (no allocs allowed) ----------------
__device__ bf16 g_xhi[(size_t)SEQ * DIN];
__device__ bf16 g_xlo[(size_t)SEQ * DIN];
__device__ bf16 g_Wqh[(size_t)QDIM * DIN],  g_Wql[(size_t)QDIM * DIN];
__device__ bf16 g_Wkh[(size_t)KVDIM * DIN], g_Wkl[(size_t)KVDIM * DIN];
__device__ bf16 g_Wvh[(size_t)KVDIM * DIN], g_Wvl[(size_t)KVDIM * DIN];
__device__ bf16 g_Woh[(size_t)DIN * QDIM],  g_Wol[(size_t)DIN * QDIM];
__device__ float g_Qp[(size_t)SEQ * QDIM];
__device__ float g_Kp[(size_t)SEQ * KVDIM];
__device__ float g_Vp[(size_t)SEQ * KVDIM];
__device__ bf16 g_Qhi[(size_t)SEQ * QDIM], g_Qlo[(size_t)SEQ * QDIM];
__device__ bf16 g_Khi[(size_t)NKV * SEQ * HD], g_Klo[(size_t)NKV * SEQ * HD];
__device__ bf16 g_Vthi[(size_t)NKV * HD * SEQ], g_Vtlo[(size_t)NKV * HD * SEQ];
__device__ float g_S[(size_t)NH * SEQ * SEQ];
__device__ bf16 g_Phi[(size_t)NH * SEQ * SEQ], g_Plo[(size_t)NH * SEQ * SEQ];
__device__ bf16 g_ctxh[(size_t)SEQ * QDIM], g_ctxl[(size_t)SEQ * QDIM];

// ---------------- helpers ----------------
__device__ __forceinline__ uint32_t smem_u32(const void* p) {
    uint32_t a;
    asm("{ .reg .u64 t; cvta.to.shared.u64 t, %1; cvt.u32.u64 %0, t; }" : "=r"(a) : "l"(p));
    return a;
}
// swizzle for tiles with 64B rows (32 bf16): permute 16B chunk by (row>>1)&3
#define SWZ64(o) ((o) ^ ((((o) >> 7) & 3u) << 4))

#define CP16(dst, src) asm volatile("cp.async.cg.shared.global [%0], [%1], 16;" :: "r"(dst), "l"(src))
#define CP_COMMIT()    asm volatile("cp.async.commit_group;" ::: "memory")
#define CP_WAIT1()     asm volatile("cp.async.wait_group 1;" ::: "memory")
#define CP_WAIT0()     asm volatile("cp.async.wait_group 0;" ::: "memory")

__device__ __forceinline__ void ldmx4(uint32_t* f, uint32_t addr) {
    asm volatile("ldmatrix.sync.aligned.m8n8.x4.shared.b16 {%0,%1,%2,%3}, [%4];"
        : "=r"(f[0]), "=r"(f[1]), "=r"(f[2]), "=r"(f[3]) : "r"(addr));
}
__device__ __forceinline__ void mma16816(float& d0, float& d1, float& d2, float& d3,
                                         const uint32_t* a, const uint32_t* b) {
    asm volatile("mma.sync.aligned.m16n8k16.row.col.f32.bf16.bf16.f32 "
        "{%0,%1,%2,%3}, {%4,%5,%6,%7}, {%8,%9}, {%0,%1,%2,%3};"
        : "+f"(d0), "+f"(d1), "+f"(d2), "+f"(d3)
        : "r"(a[0]), "r"(a[1]), "r"(a[2]), "r"(a[3]), "r"(b[0]), "r"(b[1]));
}
__device__ __forceinline__ void st_hl(bf16* hi, bf16* lo, size_t off, float a, float b) {
    bf162 h = __floats2bfloat162_rn(a, b);
    float2 f = __bfloat1622float2(h);
    bf162 l = __floats2bfloat162_rn(a - f.x, b - f.y);
    *(bf162*)(hi + off) = h;
    *(bf162*)(lo + off) = l;
}

// ---------------- bf16x3 tensor GEMM ----------------
// C[M,N] += A[M,K] @ B[N,K]^T ; A,B pre-split hi/lo bf16, both K-major.
extern __shared__ char dsm[];
__global__ void __launch_bounds__(256) gemm_bf3(
    const bf16* __restrict__ Ahi, const bf16* __restrict__ Alo,
    const bf16* __restrict__ Bhi, const bf16* __restrict__ Blo,
    float* __restrict__ C, bf16* __restrict__ Chi, bf16* __restrict__ Clo,
    int lda, int ldb, int ldc, int K,
    int causal, int a_causal,
    long long a_zs, long long b_zs, int b_zshift, long long c_zs)
{
    int z = blockIdx.z;
    int row0 = blockIdx.y * BM, col0 = blockIdx.x * BN;
    if (causal && col0 > row0 + BM - 1) return;

    size_t aoff = (size_t)z * a_zs + (size_t)row0 * lda;
    size_t boff = (size_t)(z >> b_zshift) * b_zs + (size_t)col0 * ldb;
    Ahi += aoff; Alo += aoff; Bhi += boff; Blo += boff;
    size_t coff = (size_t)z * c_zs + (size_t)row0 * ldc + col0;
    int Keff = a_causal ? min(K, row0 + BM) : K;
    int nch = Keff / BK;

    uint32_t sb = smem_u32(dsm);
    int tid = threadIdx.x;
    int lane = tid & 31, wid = tid >> 5;
    int wm = wid >> 2, wn = wid & 3;      // 2 x 4 warp grid, 64x32 per warp

    // per-thread cp.async slots: 512 16B-chunks per 8KB tile, 2 per thread
    int ida = tid, idb = tid + 256;
    int ra = ida >> 2, ca = ida & 3;
    int rb = idb >> 2, cb = idb & 3;
    uint32_t sma = SWZ64((uint32_t)(ra * 64 + ca * 16));
    uint32_t smb = SWZ64((uint32_t)(rb * 64 + cb * 16));
    size_t gAa = (size_t)ra * lda + ca * 8, gAb = (size_t)rb * lda + cb * 8;
    size_t gBa = (size_t)ra * ldb + ca * 8, gBb = (size_t)rb * ldb + cb * 8;

    float acc[4][4][4];
#pragma unroll
    for (int i = 0; i < 4; i++)
#pragma unroll
        for (int j = 0; j < 4; j++)
#pragma unroll
            for (int e = 0; e < 4; e++) acc[i][j][e] = 0.f;

    // stage s at sb + s*32768: [Ahi 0][Alo 8192][Bhi 16384][Blo 24576]
#define ISSUE(ch, s) do {                                                  \
        uint32_t st_ = sb + (s) * 32768;                                   \
        int k0_ = (ch) * BK;                                               \
        CP16(st_ + sma,          Ahi + gAa + k0_);                         \
        CP16(st_ + smb,          Ahi + gAb + k0_);                         \
        CP16(st_ + 8192  + sma,  Alo + gAa + k0_);                         \
        CP16(st_ + 8192  + smb,  Alo + gAb + k0_);                         \
        CP16(st_ + 16384 + sma,  Bhi + gBa + k0_);                         \
        CP16(st_ + 16384 + smb,  Bhi + gBb + k0_);                         \
        CP16(st_ + 24576 + sma,  Blo + gBa + k0_);                         \
        CP16(st_ + 24576 + smb,  Blo + gBb + k0_);                         \
        CP_COMMIT();                                                       \
    } while (0)

    ISSUE(0, 0);

    // fragment address components
    int a_r = lane & 15;
    int a_c = lane >> 4;                // 0/1 -> k half
    int b_q = lane >> 3;
    int b_r = (b_q >> 1) * 8 + (lane & 7);
    int b_c = b_q & 1;

    for (int ch = 0; ch < nch; ch++) {
        int s = ch & 1;
        if (ch + 1 < nch) { ISSUE(ch + 1, s ^ 1); CP_WAIT1(); }
        else               CP_WAIT0();
        __syncthreads();

        uint32_t st = sb + s * 32768;
#pragma unroll
        for (int ks = 0; ks < 2; ks++) {
            uint32_t ah[4][4], al[4][4], bh[4][2], bl[4][2];
#pragma unroll
            for (int mf = 0; mf < 4; mf++) {
                int row = wm * 64 + mf * 16 + a_r;
                uint32_t off = SWZ64((uint32_t)(row * 64 + (ks * 2 + a_c) * 16));
                ldmx4(ah[mf], st + off);
                ldmx4(al[mf], st + 8192 + off);
            }
#pragma unroll
            for (int np = 0; np < 2; np++) {
                int row = wn * 32 + np * 16 + b_r;
                uint32_t off = SWZ64((uint32_t)(row * 64 + (ks * 2 + b_c) * 16));
                uint32_t t4[4];
                ldmx4(t4, st + 16384 + off);
                bh[np*2][0] = t4[0]; bh[np*2][1] = t4[1];
                bh[np*2+1][0] = t4[2]; bh[np*2+1][1] = t4[3];
                ldmx4(t4, st + 24576 + off);
                bl[np*2][0] = t4[0]; bl[np*2][1] = t4[1];
                bl[np*2+1][0] = t4[2]; bl[np*2+1][1] = t4[3];
            }
#pragma unroll
            for (int mf = 0; mf < 4; mf++)
#pragma unroll
                for (int nf = 0; nf < 4; nf++) {
                    float* d = acc[mf][nf];
                    mma16816(d[0], d[1], d[2], d[3], ah[mf], bh[nf]);
                    mma16816(d[0], d[1], d[2], d[3], ah[mf], bl[nf]);
                    mma16816(d[0], d[1], d[2], d[3], al[mf], bh[nf]);
                }
        }
        __syncthreads();
    }

    // epilogue
    int g = lane >> 2, tg = lane & 3;
#pragma unroll
    for (int mf = 0; mf < 4; mf++)
#pragma unroll
        for (int nf = 0; nf < 4; nf++) {
            int rA = wm * 64 + mf * 16 + g;
            int cc = wn * 32 + nf * 8 + tg * 2;
            float* d = acc[mf][nf];
            if (C) {
                *(float2*)(C + coff + (size_t)rA * ldc + cc)       = make_float2(d[0], d[1]);
                *(float2*)(C + coff + (size_t)(rA + 8) * ldc + cc) = make_float2(d[2], d[3]);
            } else {
                st_hl(Chi, Clo, coff + (size_t)rA * ldc + cc,       d[0], d[1]);
                st_hl(Chi, Clo, coff + (size_t)(rA + 8) * ldc + cc, d[2], d[3]);
            }
        }
#undef ISSUE
}

// ---------------- converters ----------------
__global__ void convert_x_kernel(const float* __restrict__ x, bf16* __restrict__ hi,
                                 bf16* __restrict__ lo)
{
    size_t i = (size_t)blockIdx.x * blockDim.x + threadIdx.x;   // float4 index
    float4 v = ((const float4*)x)[i];
    bf162 h01 = __floats2bfloat162_rn(v.x, v.y);
    bf162 h23 = __floats2bfloat162_rn(v.z, v.w);
    float2 f01 = __bfloat1622float2(h01);
    float2 f23 = __bfloat1622float2(h23);
    ((bf162*)hi)[2 * i]     = h01;
    ((bf162*)hi)[2 * i + 1] = h23;
    ((bf162*)lo)[2 * i]     = __floats2bfloat162_rn(v.x - f01.x, v.y - f01.y);
    ((bf162*)lo)[2 * i + 1] = __floats2bfloat162_rn(v.z - f23.x, v.w - f23.y);
}

// W [K][N] fp32 -> Wt [N][K] hi/lo bf16
__global__ void convert_w_kernel(const float* __restrict__ W, bf16* __restrict__ hi,
                                 bf16* __restrict__ lo, int Kd, int Nd)
{
    __shared__ float tile[32][33];
    int n0 = blockIdx.x * 32, k0 = blockIdx.y * 32;
    int tx = threadIdx.x, ty = threadIdx.y;
#pragma unroll
    for (int j = 0; j < 32; j += 8)
        tile[ty + j][tx] = W[(size_t)(k0 + ty + j) * Nd + n0 + tx];
    __syncthreads();
#pragma unroll
    for (int j = 0; j < 32; j += 8) {
        int n = n0 + ty + j, k = k0 + tx;
        float v = tile[tx][ty + j];
        bf16 h = __float2bfloat16_rn(v);
        size_t off = (size_t)n * Kd + k;
        hi[off] = h;
        lo[off] = __float2bfloat16_rn(v - __bfloat162float(h));
    }
}

// ---------------- RMSNorm + RoPE -> bf16 hi/lo (+ optional fp32) ----------------
__global__ void norm_rope_kernel(
    const float* __restrict__ in, float* __restrict__ outf,
    bf16* __restrict__ outh, bf16* __restrict__ outl,
    const float* __restrict__ scale,
    const float* __restrict__ cosb, const float* __restrict__ sinb,
    int in_ts, int in_hs, int out_ts, int out_hs)
{
    int t = blockIdx.x, h = blockIdx.y, d = threadIdx.x;
    __shared__ float red[HD];
    __shared__ float sm[HD];

    float val = in[(size_t)t * in_ts + (size_t)h * in_hs + d];
    red[d] = val * val;
    __syncthreads();
#pragma unroll
    for (int s = 64; s > 0; s >>= 1) {
        if (d < s) red[d] += red[d + s];
        __syncthreads();
    }
    float rms = rsqrtf(red[0] * (1.0f / HD) + 1e-6f);
    float nv = val * rms * scale[d];
    sm[d] = nv;
    __syncthreads();
    float partner = (d < 64) ? sm[d + 64] : sm[d - 64];
    float rot = (d < 64) ? -partner : partner;
    float o = nv * cosb[t * HD + d] + rot * sinb[t * HD + d];

    size_t off = (size_t)t * out_ts + (size_t)h * out_hs + d;
    if (outf) outf[off] = o;
    bf16 hh = __float2bfloat16_rn(o);
    outh[off] = hh;
    outl[off] = __float2bfloat16_rn(o - __bfloat162float(hh));
}

// V: [t][kv*128+d] fp32 -> Vout fp32 [kv][t][d] + Vt hi/lo [kv][d][t]
__global__ void vtrans_kernel(const float* __restrict__ Vp, float* __restrict__ Vout,
                              bf16* __restrict__ Vthi, bf16* __restrict__ Vtlo)
{
    __shared__ float tile[32][33];
    int kv = blockIdx.z;
    int t0 = blockIdx.x * 32, d0 = blockIdx.y * 32;
    int tx = threadIdx.x, ty = threadIdx.y;
#pragma unroll
    for (int j = 0; j < 32; j += 8) {
        int t = t0 + ty + j;
        float v = Vp[(size_t)t * KVDIM + kv * HD + d0 + tx];
        tile[ty + j][tx] = v;
        Vout[((size_t)kv * SEQ + t) * HD + d0 + tx] = v;
    }
    __syncthreads();
#pragma unroll
    for (int j = 0; j < 32; j += 8) {
        int d = d0 + ty + j, t = t0 + tx;
        float v = tile[tx][ty + j];
        size_t off = ((size_t)kv * HD + d) * SEQ + t;
        bf16 h = __float2bfloat16_rn(v);
        Vthi[off] = h;
        Vtlo[off] = __float2bfloat16_rn(v - __bfloat162float(h));
    }
}

// ---------------- softmax: S fp32 -> P hi/lo bf16 ----------------
__global__ void __launch_bounds__(256) softmax_kernel(
    const float* __restrict__ Sg, bf16* __restrict__ Phi, bf16* __restrict__ Plo)
{
    int q = blockIdx.x, h = blockIdx.y;
    const float* row = Sg + (size_t)h * SEQ * SEQ + (size_t)q * SEQ;
    bf16* ph = Phi + (size_t)h * SEQ * SEQ + (size_t)q * SEQ;
    bf16* pl = Plo + (size_t)h * SEQ * SEQ + (size_t)q * SEQ;
    int len = q + 1;
    int qceil = ((q >> 7) + 1) << 7;
    const float scl = 0.08838834764831845f;
    __shared__ float red[256];
    int tid = threadIdx.x;

    float m = -1e30f;
    for (int i = tid; i < len; i += 256) m = fmaxf(m, row[i]);
    red[tid] = m;
    __syncthreads();
#pragma unroll
    for (int s = 128; s > 0; s >>= 1) {
        if (tid < s) red[tid] = fmaxf(red[tid], red[tid + s]);
        __syncthreads();
    }
    m = red[0] * scl;
    __syncthreads();

    float sum = 0.f;
    for (int i = tid; i < len; i += 256) sum += __expf(row[i] * scl - m);
    red[tid] = sum;
    __syncthreads();
#pragma unroll
    for (int s = 128; s > 0; s >>= 1) {
        if (tid < s) red[tid] += red[tid + s];
        __syncthreads();
    }
    float inv = 1.f / red[0];

    for (int i = tid; i < len; i += 256) {
        float p = __expf(row[i] * scl - m) * inv;
        bf16 hh = __float2bfloat16_rn(p);
        ph[i] = hh;
        pl[i] = __float2bfloat16_rn(p - __bfloat162float(hh));
    }
    for (int i = len + tid; i < qceil; i += 256) {
        ph[i] = __float2bfloat16_rn(0.f);
        pl[i] = __float2bfloat16_rn(0.f);
    }
}

// ---------------- launch ----------------
extern "C" void kernel_launch(void* const* d_in, const int* in_sizes, int n_in,
                              void* d_out, int out_size)
{
    const float* x       = (const float*)d_in[0];
    const float* Wq      = (const float*)d_in[1];
    const float* Wk      = (const float*)d_in[2];
    const float* Wv      = (const float*)d_in[3];
    const float* Wo      = (const float*)d_in[4];
    const float* q_scale = (const float*)d_in[5];
    const float* k_scale = (const float*)d_in[6];
    const float* cosb    = (const float*)d_in[7];
    const float* sinb    = (const float*)d_in[8];

    float* out  = (float*)d_out;
    float* Kout = out  + (size_t)SEQ * DIN;
    float* Vout = Kout + (size_t)NKV * SEQ * HD;

    bf16 *xhi, *xlo, *Wqh, *Wql, *Wkh, *Wkl, *Wvh, *Wvl, *Woh, *Wol;
    bf16 *Qhi, *Qlo, *Khi, *Klo, *Vthi, *Vtlo, *Phi, *Plo, *ctxh, *ctxl;
    float *Qp, *Kp, *Vp, *S;
    cudaGetSymbolAddress((void**)&xhi, g_xhi);   cudaGetSymbolAddress((void**)&xlo, g_xlo);
    cudaGetSymbolAddress((void**)&Wqh, g_Wqh);   cudaGetSymbolAddress((void**)&Wql, g_Wql);
    cudaGetSymbolAddress((void**)&Wkh, g_Wkh);   cudaGetSymbolAddress((void**)&Wkl, g_Wkl);
    cudaGetSymbolAddress((void**)&Wvh, g_Wvh);   cudaGetSymbolAddress((void**)&Wvl, g_Wvl);
    cudaGetSymbolAddress((void**)&Woh, g_Woh);   cudaGetSymbolAddress((void**)&Wol, g_Wol);
    cudaGetSymbolAddress((void**)&Qp, g_Qp);     cudaGetSymbolAddress((void**)&Kp, g_Kp);
    cudaGetSymbolAddress((void**)&Vp, g_Vp);     cudaGetSymbolAddress((void**)&S, g_S);
    cudaGetSymbolAddress((void**)&Qhi, g_Qhi);   cudaGetSymbolAddress((void**)&Qlo, g_Qlo);
    cudaGetSymbolAddress((void**)&Khi, g_Khi);   cudaGetSymbolAddress((void**)&Klo, g_Klo);
    cudaGetSymbolAddress((void**)&Vthi, g_Vthi); cudaGetSymbolAddress((void**)&Vtlo, g_Vtlo);
    cudaGetSymbolAddress((void**)&Phi, g_Phi);   cudaGetSymbolAddress((void**)&Plo, g_Plo);
    cudaGetSymbolAddress((void**)&ctxh, g_ctxh); cudaGetSymbolAddress((void**)&ctxl, g_ctxl);

    const int SMEM = 65536;
    cudaFuncSetAttribute(gemm_bf3, cudaFuncAttributeMaxDynamicSharedMemorySize, SMEM);

    dim3 blk(256);
    dim3 tblk(32, 8);

    // input conversions
    convert_x_kernel<<<(SEQ * DIN / 4) / 256, 256>>>(x, xhi, xlo);
    convert_w_kernel<<<dim3(QDIM / 32,  DIN / 32),  tblk>>>(Wq, Wqh, Wql, DIN, QDIM);
    convert_w_kernel<<<dim3(KVDIM / 32, DIN / 32),  tblk>>>(Wk, Wkh, Wkl, DIN, KVDIM);
    convert_w_kernel<<<dim3(KVDIM / 32, DIN / 32),  tblk>>>(Wv, Wvh, Wvl, DIN, KVDIM);
    convert_w_kernel<<<dim3(DIN / 32,   QDIM / 32), tblk>>>(Wo, Woh, Wol, QDIM, DIN);

    // projections (C fp32)
    gemm_bf3<<<dim3(QDIM / BN,  SEQ / BM, 1), blk, SMEM>>>(
        xhi, xlo, Wqh, Wql, Qp, nullptr, nullptr, DIN, DIN, QDIM, DIN, 0, 0, 0, 0, 0, 0);
    gemm_bf3<<<dim3(KVDIM / BN, SEQ / BM, 1), blk, SMEM>>>(
        xhi, xlo, Wkh, Wkl, Kp, nullptr, nullptr, DIN, DIN, KVDIM, DIN, 0, 0, 0, 0, 0, 0);
    gemm_bf3<<<dim3(KVDIM / BN, SEQ / BM, 1), blk, SMEM>>>(
        xhi, xlo, Wvh, Wvl, Vp, nullptr, nullptr, DIN, DIN, KVDIM, DIN, 0, 0, 0, 0, 0, 0);

    // norm+rope: Q -> hi/lo [t][4096]; K -> fp32 Kout + hi/lo [kv][t][d]
    norm_rope_kernel<<<dim3(SEQ, NH),  HD>>>(Qp, nullptr, Qhi, Qlo, q_scale, cosb, sinb,
                                             QDIM, HD, QDIM, HD);
    norm_rope_kernel<<<dim3(SEQ, NKV), HD>>>(Kp, Kout, Khi, Klo, k_scale, cosb, sinb,
                                             KVDIM, HD, HD, SEQ * HD);
    vtrans_kernel<<<dim3(SEQ / 32, HD / 32, NKV), tblk>>>(Vp, Vout, Vthi, Vtlo);

    // scores: S[h] = Q_h @ K_kv^T (causal tile skip)
    gemm_bf3<<<dim3(SEQ / BN, SEQ / BM, NH), blk, SMEM>>>(
        Qhi, Qlo, Khi, Klo, S, nullptr, nullptr,
        QDIM, HD, SEQ, HD, 1, 0,
        (long long)HD, (long long)SEQ * HD, 2, (long long)SEQ * SEQ);

    softmax_kernel<<<dim3(SEQ, NH), blk>>>(S, Phi, Plo);

    // PV: ctx_h = P_h @ V_kv (B = V^T [d][t]), causal K bound; C -> ctx hi/lo
    gemm_bf3<<<dim3(1, SEQ / BM, NH), blk, SMEM>>>(
        Phi, Plo, Vthi, Vtlo, nullptr, ctxh, ctxl,
        SEQ, SEQ, QDIM, SEQ, 0, 1,
        (long long)SEQ * SEQ, (long long)HD * SEQ, 2, (long long)HD);

    // out projection
    gemm_bf3<<<dim3(DIN / BN, SEQ / BM, 1), blk, SMEM>>>(
        ctxh, ctxl, Woh, Wol, out, nullptr, nullptr,
        QDIM, QDIM, DIN, QDIM, 0, 0, 0, 0, 0, 0);
}

// round 4
// speedup vs baseline: 2.8213x; 1.1049x over previous
#include <cuda_runtime.h>
#include <cuda_bf16.h>
#include <cstdint>

#define SEQ 2048
#define DIN 2048
#define NH 32
#define NKV 8
#define HD 128
#define QDIM 4096
#define KVDIM 1024

typedef __nv_bfloat16 bf16;
typedef __nv_bfloat162 bf162;

#define BM 128
#define BN 128
#define BK 32

// ---------------- static scratch (no allocs allowed) ----------------
__device__ bf16 g_xhi[(size_t)SEQ * DIN];
__device__ bf16 g_xlo[(size_t)SEQ * DIN];
__device__ bf16 g_Wqh[(size_t)QDIM * DIN],  g_Wql[(size_t)QDIM * DIN];
__device__ bf16 g_Wkh[(size_t)KVDIM * DIN], g_Wkl[(size_t)KVDIM * DIN];
__device__ bf16 g_Wvh[(size_t)KVDIM * DIN], g_Wvl[(size_t)KVDIM * DIN];
__device__ bf16 g_Woh[(size_t)DIN * QDIM],  g_Wol[(size_t)DIN * QDIM];
__device__ float g_Qp[(size_t)SEQ * QDIM];
__device__ float g_Kp[(size_t)SEQ * KVDIM];
__device__ float g_Vp[(size_t)SEQ * KVDIM];
__device__ bf16 g_Qhi[(size_t)SEQ * QDIM], g_Qlo[(size_t)SEQ * QDIM];
__device__ bf16 g_Khi[(size_t)NKV * SEQ * HD], g_Klo[(size_t)NKV * SEQ * HD];
__device__ bf16 g_Vthi[(size_t)NKV * HD * SEQ], g_Vtlo[(size_t)NKV * HD * SEQ];
__device__ float g_S[(size_t)NH * SEQ * SEQ];
__device__ bf16 g_Phi[(size_t)NH * SEQ * SEQ], g_Plo[(size_t)NH * SEQ * SEQ];
__device__ bf16 g_ctxh[(size_t)SEQ * QDIM], g_ctxl[(size_t)SEQ * QDIM];

// ---------------- helpers ----------------
__device__ __forceinline__ uint32_t smem_u32(const void* p) {
    uint32_t a;
    asm("{ .reg .u64 t; cvta.to.shared.u64 t, %1; cvt.u32.u64 %0, t; }" : "=r"(a) : "l"(p));
    return a;
}
// swizzle for tiles with 64B rows (32 bf16): permute 16B chunk by (row>>1)&3
#define SWZ64(o) ((o) ^ ((((o) >> 7) & 3u) << 4))

#define CP16(dst, src) asm volatile("cp.async.cg.shared.global [%0], [%1], 16;" :: "r"(dst), "l"(src))
#define CP_COMMIT()    asm volatile("cp.async.commit_group;" ::: "memory")
#define CP_WAIT1()     asm volatile("cp.async.wait_group 1;" ::: "memory")
#define CP_WAIT0()     asm volatile("cp.async.wait_group 0;" ::: "memory")

__device__ __forceinline__ void ldmx4(uint32_t* f, uint32_t addr) {
    asm volatile("ldmatrix.sync.aligned.m8n8.x4.shared.b16 {%0,%1,%2,%3}, [%4];"
        : "=r"(f[0]), "=r"(f[1]), "=r"(f[2]), "=r"(f[3]) : "r"(addr));
}
__device__ __forceinline__ void mma16816(float* d, const uint32_t* a, const uint32_t* b) {
    asm volatile("mma.sync.aligned.m16n8k16.row.col.f32.bf16.bf16.f32 "
        "{%0,%1,%2,%3}, {%4,%5,%6,%7}, {%8,%9}, {%0,%1,%2,%3};"
        : "+f"(d[0]), "+f"(d[1]), "+f"(d[2]), "+f"(d[3])
        : "r"(a[0]), "r"(a[1]), "r"(a[2]), "r"(a[3]), "r"(b[0]), "r"(b[1]));
}
__device__ __forceinline__ void st_hl(bf16* hi, bf16* lo, size_t off, float a, float b) {
    bf162 h = __floats2bfloat162_rn(a, b);
    float2 f = __bfloat1622float2(h);
    bf162 l = __floats2bfloat162_rn(a - f.x, b - f.y);
    *(bf162*)(hi + off) = h;
    *(bf162*)(lo + off) = l;
}

// ---------------- bf16x3 tensor GEMM (v2: 4 warps, 64x64 warp tile, 3-stage) -----
// C[M,N] += A[M,K] @ B[N,K]^T ; A,B pre-split hi/lo bf16, both K-major.
extern __shared__ char dsm[];
__global__ void __launch_bounds__(128, 2) gemm_bf3(
    const bf16* __restrict__ Ahi, const bf16* __restrict__ Alo,
    const bf16* __restrict__ Bhi, const bf16* __restrict__ Blo,
    float* __restrict__ C, bf16* __restrict__ Chi, bf16* __restrict__ Clo,
    int lda, int ldb, int ldc, int K,
    int causal, int a_causal,
    long long a_zs, long long b_zs, int b_zshift, long long c_zs)
{
    int z = blockIdx.z;
    int row0 = blockIdx.y * BM, col0 = blockIdx.x * BN;
    if (causal && col0 > row0 + BM - 1) return;

    size_t aoff = (size_t)z * a_zs + (size_t)row0 * lda;
    size_t boff = (size_t)(z >> b_zshift) * b_zs + (size_t)col0 * ldb;
    Ahi += aoff; Alo += aoff; Bhi += boff; Blo += boff;
    size_t coff = (size_t)z * c_zs + (size_t)row0 * ldc + col0;
    int Keff = a_causal ? min(K, row0 + BM) : K;
    int nch = Keff / BK;

    uint32_t sb = smem_u32(dsm);
    int tid = threadIdx.x;
    int lane = tid & 31, wid = tid >> 5;
    int wm = wid >> 1, wn = wid & 1;       // 2x2 warp grid, 64x64 per warp

    // cp.async slots: 512 16B-chunks per 8KB quadrant, 4 per thread
    uint32_t smo[4];
    size_t gA[4], gB[4];
#pragma unroll
    for (int i = 0; i < 4; i++) {
        int id = tid + i * 128;
        int r = id >> 2, c = id & 3;
        smo[i] = SWZ64((uint32_t)(r * 64 + c * 16));
        gA[i] = (size_t)r * lda + c * 8;
        gB[i] = (size_t)r * ldb + c * 8;
    }

    float acc[4][8][4];
#pragma unroll
    for (int i = 0; i < 4; i++)
#pragma unroll
        for (int j = 0; j < 8; j++)
#pragma unroll
            for (int e = 0; e < 4; e++) acc[i][j][e] = 0.f;

    // stage s at sb + s*32768: [Ahi 0][Alo 8192][Bhi 16384][Blo 24576]
#define ISSUE(ch, s) do {                                                  \
        uint32_t st_ = sb + (uint32_t)(s) * 32768u;                        \
        int k0_ = (ch) * BK;                                               \
        _Pragma("unroll")                                                  \
        for (int i_ = 0; i_ < 4; i_++) {                                   \
            CP16(st_ + smo[i_],          Ahi + gA[i_] + k0_);              \
            CP16(st_ + 8192  + smo[i_],  Alo + gA[i_] + k0_);              \
            CP16(st_ + 16384 + smo[i_],  Bhi + gB[i_] + k0_);              \
            CP16(st_ + 24576 + smo[i_],  Blo + gB[i_] + k0_);              \
        }                                                                  \
        CP_COMMIT();                                                       \
    } while (0)

    ISSUE(0, 0);
    if (nch > 1) ISSUE(1, 1);

    // fragment address components
    int a_r = lane & 15;
    int a_c = lane >> 4;                 // 0/1 -> 16B half of k-chunk16
    int b_q = lane >> 3;
    int b_r = (b_q >> 1) * 8 + (lane & 7);
    int b_c = b_q & 1;

    for (int ch = 0; ch < nch; ch++) {
        if (ch + 1 < nch) CP_WAIT1(); else CP_WAIT0();
        __syncthreads();
        if (ch + 2 < nch) ISSUE(ch + 2, (ch + 2) % 3);

        uint32_t st = sb + (uint32_t)(ch % 3) * 32768u;
#pragma unroll
        for (int ks = 0; ks < 2; ks++) {
            uint32_t ah[4][4], al[4][4];
#pragma unroll
            for (int mf = 0; mf < 4; mf++) {
                int row = wm * 64 + mf * 16 + a_r;
                uint32_t off = SWZ64((uint32_t)(row * 64 + (ks * 2 + a_c) * 16));
                ldmx4(ah[mf], st + off);
                ldmx4(al[mf], st + 8192 + off);
            }
#pragma unroll
            for (int np = 0; np < 4; np++) {
                int row = wn * 64 + np * 16 + b_r;
                uint32_t off = SWZ64((uint32_t)(row * 64 + (ks * 2 + b_c) * 16));
                uint32_t bh4[4], bl4[4];
                ldmx4(bh4, st + 16384 + off);
                ldmx4(bl4, st + 24576 + off);
#pragma unroll
                for (int mf = 0; mf < 4; mf++) {
                    float* d0 = acc[mf][np * 2];
                    mma16816(d0, ah[mf], bh4);
                    mma16816(d0, ah[mf], bl4);
                    mma16816(d0, al[mf], bh4);
                    float* d1 = acc[mf][np * 2 + 1];
                    mma16816(d1, ah[mf], bh4 + 2);
                    mma16816(d1, ah[mf], bl4 + 2);
                    mma16816(d1, al[mf], bh4 + 2);
                }
            }
        }
        __syncthreads();
    }

    // epilogue
    int g = lane >> 2, tg = lane & 3;
#pragma unroll
    for (int mf = 0; mf < 4; mf++)
#pragma unroll
        for (int nf = 0; nf < 8; nf++) {
            int rA = wm * 64 + mf * 16 + g;
            int cc = wn * 64 + nf * 8 + tg * 2;
            float* d = acc[mf][nf];
            if (C) {
                *(float2*)(C + coff + (size_t)rA * ldc + cc)       = make_float2(d[0], d[1]);
                *(float2*)(C + coff + (size_t)(rA + 8) * ldc + cc) = make_float2(d[2], d[3]);
            } else {
                st_hl(Chi, Clo, coff + (size_t)rA * ldc + cc,       d[0], d[1]);
                st_hl(Chi, Clo, coff + (size_t)(rA + 8) * ldc + cc, d[2], d[3]);
            }
        }
#undef ISSUE
}

// ---------------- converters ----------------
__global__ void convert_x_kernel(const float* __restrict__ x, bf16* __restrict__ hi,
                                 bf16* __restrict__ lo)
{
    size_t i = (size_t)blockIdx.x * blockDim.x + threadIdx.x;   // float4 index
    float4 v = ((const float4*)x)[i];
    bf162 h01 = __floats2bfloat162_rn(v.x, v.y);
    bf162 h23 = __floats2bfloat162_rn(v.z, v.w);
    float2 f01 = __bfloat1622float2(h01);
    float2 f23 = __bfloat1622float2(h23);
    ((bf162*)hi)[2 * i]     = h01;
    ((bf162*)hi)[2 * i + 1] = h23;
    ((bf162*)lo)[2 * i]     = __floats2bfloat162_rn(v.x - f01.x, v.y - f01.y);
    ((bf162*)lo)[2 * i + 1] = __floats2bfloat162_rn(v.z - f23.x, v.w - f23.y);
}

// W [K][N] fp32 -> Wt [N][K] hi/lo bf16
__global__ void convert_w_kernel(const float* __restrict__ W, bf16* __restrict__ hi,
                                 bf16* __restrict__ lo, int Kd, int Nd)
{
    __shared__ float tile[32][33];
    int n0 = blockIdx.x * 32, k0 = blockIdx.y * 32;
    int tx = threadIdx.x, ty = threadIdx.y;
#pragma unroll
    for (int j = 0; j < 32; j += 8)
        tile[ty + j][tx] = W[(size_t)(k0 + ty + j) * Nd + n0 + tx];
    __syncthreads();
#pragma unroll
    for (int j = 0; j < 32; j += 8) {
        int n = n0 + ty + j, k = k0 + tx;
        float v = tile[tx][ty + j];
        bf16 h = __float2bfloat16_rn(v);
        size_t off = (size_t)n * Kd + k;
        hi[off] = h;
        lo[off] = __float2bfloat16_rn(v - __bfloat162float(h));
    }
}

// ---------------- RMSNorm + RoPE -> bf16 hi/lo (+ optional fp32) ----------------
__global__ void norm_rope_kernel(
    const float* __restrict__ in, float* __restrict__ outf,
    bf16* __restrict__ outh, bf16* __restrict__ outl,
    const float* __restrict__ scale,
    const float* __restrict__ cosb, const float* __restrict__ sinb,
    int in_ts, int in_hs, int out_ts, int out_hs)
{
    int t = blockIdx.x, h = blockIdx.y, d = threadIdx.x;
    __shared__ float red[HD];
    __shared__ float sm[HD];

    float val = in[(size_t)t * in_ts + (size_t)h * in_hs + d];
    red[d] = val * val;
    __syncthreads();
#pragma unroll
    for (int s = 64; s > 0; s >>= 1) {
        if (d < s) red[d] += red[d + s];
        __syncthreads();
    }
    float rms = rsqrtf(red[0] * (1.0f / HD) + 1e-6f);
    float nv = val * rms * scale[d];
    sm[d] = nv;
    __syncthreads();
    float partner = (d < 64) ? sm[d + 64] : sm[d - 64];
    float rot = (d < 64) ? -partner : partner;
    float o = nv * cosb[t * HD + d] + rot * sinb[t * HD + d];

    size_t off = (size_t)t * out_ts + (size_t)h * out_hs + d;
    if (outf) outf[off] = o;
    bf16 hh = __float2bfloat16_rn(o);
    outh[off] = hh;
    outl[off] = __float2bfloat16_rn(o - __bfloat162float(hh));
}

// V: [t][kv*128+d] fp32 -> Vout fp32 [kv][t][d] + Vt hi/lo [kv][d][t]
__global__ void vtrans_kernel(const float* __restrict__ Vp, float* __restrict__ Vout,
                              bf16* __restrict__ Vthi, bf16* __restrict__ Vtlo)
{
    __shared__ float tile[32][33];
    int kv = blockIdx.z;
    int t0 = blockIdx.x * 32, d0 = blockIdx.y * 32;
    int tx = threadIdx.x, ty = threadIdx.y;
#pragma unroll
    for (int j = 0; j < 32; j += 8) {
        int t = t0 + ty + j;
        float v = Vp[(size_t)t * KVDIM + kv * HD + d0 + tx];
        tile[ty + j][tx] = v;
        Vout[((size_t)kv * SEQ + t) * HD + d0 + tx] = v;
    }
    __syncthreads();
#pragma unroll
    for (int j = 0; j < 32; j += 8) {
        int d = d0 + ty + j, t = t0 + tx;
        float v = tile[tx][ty + j];
        size_t off = ((size_t)kv * HD + d) * SEQ + t;
        bf16 h = __float2bfloat16_rn(v);
        Vthi[off] = h;
        Vtlo[off] = __float2bfloat16_rn(v - __bfloat162float(h));
    }
}

// ---------------- softmax: S fp32 -> P hi/lo bf16 (smem row cache) ----------------
__global__ void __launch_bounds__(256) softmax_kernel(
    const float* __restrict__ Sg, bf16* __restrict__ Phi, bf16* __restrict__ Plo)
{
    float* srow = (float*)dsm;             // 2048 floats
    float* red  = (float*)(dsm + 8192);    // 256 floats
    int q = blockIdx.x, h = blockIdx.y;
    const float* row = Sg + (size_t)h * SEQ * SEQ + (size_t)q * SEQ;
    bf16* ph = Phi + (size_t)h * SEQ * SEQ + (size_t)q * SEQ;
    bf16* pl = Plo + (size_t)h * SEQ * SEQ + (size_t)q * SEQ;
    int len = q + 1;
    int qceil = ((q >> 7) + 1) << 7;
    const float scl = 0.08838834764831845f;
    int tid = threadIdx.x;

    float m = -1e30f;
    for (int i = tid; i < len; i += 256) {
        float v = row[i] * scl;
        srow[i] = v;
        m = fmaxf(m, v);
    }
    red[tid] = m;
    __syncthreads();
#pragma unroll
    for (int s = 128; s > 0; s >>= 1) {
        if (tid < s) red[tid] = fmaxf(red[tid], red[tid + s]);
        __syncthreads();
    }
    m = red[0];
    __syncthreads();

    float sum = 0.f;
    for (int i = tid; i < len; i += 256) {
        float e = __expf(srow[i] - m);
        srow[i] = e;
        sum += e;
    }
    red[tid] = sum;
    __syncthreads();
#pragma unroll
    for (int s = 128; s > 0; s >>= 1) {
        if (tid < s) red[tid] += red[tid + s];
        __syncthreads();
    }
    float inv = 1.f / red[0];

    for (int i = tid; i < len; i += 256) {
        float p = srow[i] * inv;
        bf16 hh = __float2bfloat16_rn(p);
        ph[i] = hh;
        pl[i] = __float2bfloat16_rn(p - __bfloat162float(hh));
    }
    bf16 z = __float2bfloat16_rn(0.f);
    for (int i = len + tid; i < qceil; i += 256) {
        ph[i] = z;
        pl[i] = z;
    }
}

// ---------------- launch ----------------
extern "C" void kernel_launch(void* const* d_in, const int* in_sizes, int n_in,
                              void* d_out, int out_size)
{
    const float* x       = (const float*)d_in[0];
    const float* Wq      = (const float*)d_in[1];
    const float* Wk      = (const float*)d_in[2];
    const float* Wv      = (const float*)d_in[3];
    const float* Wo      = (const float*)d_in[4];
    const float* q_scale = (const float*)d_in[5];
    const float* k_scale = (const float*)d_in[6];
    const float* cosb    = (const float*)d_in[7];
    const float* sinb    = (const float*)d_in[8];

    float* out  = (float*)d_out;
    float* Kout = out  + (size_t)SEQ * DIN;
    float* Vout = Kout + (size_t)NKV * SEQ * HD;

    bf16 *xhi, *xlo, *Wqh, *Wql, *Wkh, *Wkl, *Wvh, *Wvl, *Woh, *Wol;
    bf16 *Qhi, *Qlo, *Khi, *Klo, *Vthi, *Vtlo, *Phi, *Plo, *ctxh, *ctxl;
    float *Qp, *Kp, *Vp, *S;
    cudaGetSymbolAddress((void**)&xhi, g_xhi);   cudaGetSymbolAddress((void**)&xlo, g_xlo);
    cudaGetSymbolAddress((void**)&Wqh, g_Wqh);   cudaGetSymbolAddress((void**)&Wql, g_Wql);
    cudaGetSymbolAddress((void**)&Wkh, g_Wkh);   cudaGetSymbolAddress((void**)&Wkl, g_Wkl);
    cudaGetSymbolAddress((void**)&Wvh, g_Wvh);   cudaGetSymbolAddress((void**)&Wvl, g_Wvl);
    cudaGetSymbolAddress((void**)&Woh, g_Woh);   cudaGetSymbolAddress((void**)&Wol, g_Wol);
    cudaGetSymbolAddress((void**)&Qp, g_Qp);     cudaGetSymbolAddress((void**)&Kp, g_Kp);
    cudaGetSymbolAddress((void**)&Vp, g_Vp);     cudaGetSymbolAddress((void**)&S, g_S);
    cudaGetSymbolAddress((void**)&Qhi, g_Qhi);   cudaGetSymbolAddress((void**)&Qlo, g_Qlo);
    cudaGetSymbolAddress((void**)&Khi, g_Khi);   cudaGetSymbolAddress((void**)&Klo, g_Klo);
    cudaGetSymbolAddress((void**)&Vthi, g_Vthi); cudaGetSymbolAddress((void**)&Vtlo, g_Vtlo);
    cudaGetSymbolAddress((void**)&Phi, g_Phi);   cudaGetSymbolAddress((void**)&Plo, g_Plo);
    cudaGetSymbolAddress((void**)&ctxh, g_ctxh); cudaGetSymbolAddress((void**)&ctxl, g_ctxl);

    const int SMEM = 3 * 32768;   // 98304
    cudaFuncSetAttribute(gemm_bf3, cudaFuncAttributeMaxDynamicSharedMemorySize, SMEM);

    dim3 blk(128);
    dim3 tblk(32, 8);

    // input conversions
    convert_x_kernel<<<(SEQ * DIN / 4) / 256, 256>>>(x, xhi, xlo);
    convert_w_kernel<<<dim3(QDIM / 32,  DIN / 32),  tblk>>>(Wq, Wqh, Wql, DIN, QDIM);
    convert_w_kernel<<<dim3(KVDIM / 32, DIN / 32),  tblk>>>(Wk, Wkh, Wkl, DIN, KVDIM);
    convert_w_kernel<<<dim3(KVDIM / 32, DIN / 32),  tblk>>>(Wv, Wvh, Wvl, DIN, KVDIM);
    convert_w_kernel<<<dim3(DIN / 32,   QDIM / 32), tblk>>>(Wo, Woh, Wol, QDIM, DIN);

    // projections (C fp32)
    gemm_bf3<<<dim3(QDIM / BN,  SEQ / BM, 1), blk, SMEM>>>(
        xhi, xlo, Wqh, Wql, Qp, nullptr, nullptr, DIN, DIN, QDIM, DIN, 0, 0, 0, 0, 0, 0);
    gemm_bf3<<<dim3(KVDIM / BN, SEQ / BM, 1), blk, SMEM>>>(
        xhi, xlo, Wkh, Wkl, Kp, nullptr, nullptr, DIN, DIN, KVDIM, DIN, 0, 0, 0, 0, 0, 0);
    gemm_bf3<<<dim3(KVDIM / BN, SEQ / BM, 1), blk, SMEM>>>(
        xhi, xlo, Wvh, Wvl, Vp, nullptr, nullptr, DIN, DIN, KVDIM, DIN, 0, 0, 0, 0, 0, 0);

    // norm+rope: Q -> hi/lo [t][4096]; K -> fp32 Kout + hi/lo [kv][t][d]
    norm_rope_kernel<<<dim3(SEQ, NH),  HD>>>(Qp, nullptr, Qhi, Qlo, q_scale, cosb, sinb,
                                             QDIM, HD, QDIM, HD);
    norm_rope_kernel<<<dim3(SEQ, NKV), HD>>>(Kp, Kout, Khi, Klo, k_scale, cosb, sinb,
                                             KVDIM, HD, HD, SEQ * HD);
    vtrans_kernel<<<dim3(SEQ / 32, HD / 32, NKV), tblk>>>(Vp, Vout, Vthi, Vtlo);

    // scores: S[h] = Q_h @ K_kv^T (causal tile skip)
    gemm_bf3<<<dim3(SEQ / BN, SEQ / BM, NH), blk, SMEM>>>(
        Qhi, Qlo, Khi, Klo, S, nullptr, nullptr,
        QDIM, HD, SEQ, HD, 1, 0,
        (long long)HD, (long long)SEQ * HD, 2, (long long)SEQ * SEQ);

    softmax_kernel<<<dim3(SEQ, NH), 256, 9216>>>(S, Phi, Plo);

    // PV: ctx_h = P_h @ V_kv (B = V^T [d][t]), causal K bound; C -> ctx hi/lo
    gemm_bf3<<<dim3(1, SEQ / BM, NH), blk, SMEM>>>(
        Phi, Plo, Vthi, Vtlo, nullptr, ctxh, ctxl,
        SEQ, SEQ, QDIM, SEQ, 0, 1,
        (long long)SEQ * SEQ, (long long)HD * SEQ, 2, (long long)HD);

    // out projection
    gemm_bf3<<<dim3(DIN / BN, SEQ / BM, 1), blk, SMEM>>>(
        ctxh, ctxl, Woh, Wol, out, nullptr, nullptr,
        QDIM, QDIM, DIN, QDIM, 0, 0, 0, 0, 0, 0);
}

// round 5
// speedup vs baseline: 3.5698x; 1.2653x over previous
#include <cuda_runtime.h>
#include <cuda_bf16.h>
#include <cstdint>

#define SEQ 2048
#define DIN 2048
#define NH 32
#define NKV 8
#define HD 128
#define QDIM 4096
#define KVDIM 1024

typedef __nv_bfloat16 bf16;
typedef __nv_bfloat162 bf162;

#define BM 128
#define BN 128
#define BK 32

// ---------------- static scratch (no allocs allowed) ----------------
__device__ bf16 g_xhi[(size_t)SEQ * DIN];
__device__ bf16 g_xlo[(size_t)SEQ * DIN];
__device__ bf16 g_Wqh[(size_t)QDIM * DIN],  g_Wql[(size_t)QDIM * DIN];
__device__ bf16 g_Wkh[(size_t)KVDIM * DIN], g_Wkl[(size_t)KVDIM * DIN];
__device__ bf16 g_Wvh[(size_t)KVDIM * DIN], g_Wvl[(size_t)KVDIM * DIN];
__device__ bf16 g_Woh[(size_t)DIN * QDIM],  g_Wol[(size_t)DIN * QDIM];
__device__ float g_Qp[(size_t)SEQ * QDIM];
__device__ float g_Kp[(size_t)SEQ * KVDIM];
__device__ float g_Vp[(size_t)SEQ * KVDIM];
__device__ bf16 g_Qhi[(size_t)SEQ * QDIM], g_Qlo[(size_t)SEQ * QDIM];
__device__ bf16 g_Khi[(size_t)NKV * SEQ * HD], g_Klo[(size_t)NKV * SEQ * HD];
__device__ bf16 g_Vthi[(size_t)NKV * HD * SEQ], g_Vtlo[(size_t)NKV * HD * SEQ];
__device__ bf16 g_ctxh[(size_t)SEQ * QDIM], g_ctxl[(size_t)SEQ * QDIM];

// ---------------- helpers ----------------
__device__ __forceinline__ uint32_t smem_u32(const void* p) {
    uint32_t a;
    asm("{ .reg .u64 t; cvta.to.shared.u64 t, %1; cvt.u32.u64 %0, t; }" : "=r"(a) : "l"(p));
    return a;
}
// swizzle for tiles with 64B rows (32 bf16): permute 16B chunk by (row>>1)&3
#define SWZ64(o) ((o) ^ ((((o) >> 7) & 3u) << 4))

#define CP16(dst, src) asm volatile("cp.async.cg.shared.global [%0], [%1], 16;" :: "r"(dst), "l"(src))
#define CP_COMMIT()    asm volatile("cp.async.commit_group;" ::: "memory")
#define CP_WAIT1()     asm volatile("cp.async.wait_group 1;" ::: "memory")
#define CP_WAIT0()     asm volatile("cp.async.wait_group 0;" ::: "memory")

__device__ __forceinline__ void ldmx4(uint32_t* f, uint32_t addr) {
    asm volatile("ldmatrix.sync.aligned.m8n8.x4.shared.b16 {%0,%1,%2,%3}, [%4];"
        : "=r"(f[0]), "=r"(f[1]), "=r"(f[2]), "=r"(f[3]) : "r"(addr));
}
__device__ __forceinline__ void mma16816(float* d, const uint32_t* a, const uint32_t* b) {
    asm volatile("mma.sync.aligned.m16n8k16.row.col.f32.bf16.bf16.f32 "
        "{%0,%1,%2,%3}, {%4,%5,%6,%7}, {%8,%9}, {%0,%1,%2,%3};"
        : "+f"(d[0]), "+f"(d[1]), "+f"(d[2]), "+f"(d[3])
        : "r"(a[0]), "r"(a[1]), "r"(a[2]), "r"(a[3]), "r"(b[0]), "r"(b[1]));
}
__device__ __forceinline__ void st_hl(bf16* hi, bf16* lo, size_t off, float a, float b) {
    bf162 h = __floats2bfloat162_rn(a, b);
    float2 f = __bfloat1622float2(h);
    bf162 l = __floats2bfloat162_rn(a - f.x, b - f.y);
    *(bf162*)(hi + off) = h;
    *(bf162*)(lo + off) = l;
}
__device__ __forceinline__ void pack_hl(float x, float y, uint32_t& hp, uint32_t& lp) {
    bf162 h = __floats2bfloat162_rn(x, y);
    float2 f = __bfloat1622float2(h);
    bf162 l = __floats2bfloat162_rn(x - f.x, y - f.y);
    hp = *(uint32_t*)&h;
    lp = *(uint32_t*)&l;
}

// ---------------- bf16x3 tensor GEMM (4 warps, 64x64 warp tile, 3-stage) -----
// C[M,N] += A[M,K] @ B[N,K]^T ; A,B pre-split hi/lo bf16, both K-major.
extern __shared__ char dsm[];
__global__ void __launch_bounds__(128, 2) gemm_bf3(
    const bf16* __restrict__ Ahi, const bf16* __restrict__ Alo,
    const bf16* __restrict__ Bhi, const bf16* __restrict__ Blo,
    float* __restrict__ C, bf16* __restrict__ Chi, bf16* __restrict__ Clo,
    int lda, int ldb, int ldc, int K)
{
    int row0 = blockIdx.y * BM, col0 = blockIdx.x * BN;
    size_t aoff = (size_t)row0 * lda;
    size_t boff = (size_t)col0 * ldb;
    Ahi += aoff; Alo += aoff; Bhi += boff; Blo += boff;
    size_t coff = (size_t)row0 * ldc + col0;
    int nch = K / BK;

    uint32_t sb = smem_u32(dsm);
    int tid = threadIdx.x;
    int lane = tid & 31, wid = tid >> 5;
    int wm = wid >> 1, wn = wid & 1;

    uint32_t smo[4];
    size_t gA[4], gB[4];
#pragma unroll
    for (int i = 0; i < 4; i++) {
        int id = tid + i * 128;
        int r = id >> 2, c = id & 3;
        smo[i] = SWZ64((uint32_t)(r * 64 + c * 16));
        gA[i] = (size_t)r * lda + c * 8;
        gB[i] = (size_t)r * ldb + c * 8;
    }

    float acc[4][8][4];
#pragma unroll
    for (int i = 0; i < 4; i++)
#pragma unroll
        for (int j = 0; j < 8; j++)
#pragma unroll
            for (int e = 0; e < 4; e++) acc[i][j][e] = 0.f;

#define ISSUE(ch, s) do {                                                  \
        uint32_t st_ = sb + (uint32_t)(s) * 32768u;                        \
        int k0_ = (ch) * BK;                                               \
        _Pragma("unroll")                                                  \
        for (int i_ = 0; i_ < 4; i_++) {                                   \
            CP16(st_ + smo[i_],          Ahi + gA[i_] + k0_);              \
            CP16(st_ + 8192  + smo[i_],  Alo + gA[i_] + k0_);              \
            CP16(st_ + 16384 + smo[i_],  Bhi + gB[i_] + k0_);              \
            CP16(st_ + 24576 + smo[i_],  Blo + gB[i_] + k0_);              \
        }                                                                  \
        CP_COMMIT();                                                       \
    } while (0)

    ISSUE(0, 0);
    if (nch > 1) ISSUE(1, 1);

    int a_r = lane & 15;
    int a_c = lane >> 4;
    int b_q = lane >> 3;
    int b_r = (b_q >> 1) * 8 + (lane & 7);
    int b_c = b_q & 1;

    for (int ch = 0; ch < nch; ch++) {
        if (ch + 1 < nch) CP_WAIT1(); else CP_WAIT0();
        __syncthreads();
        if (ch + 2 < nch) ISSUE(ch + 2, (ch + 2) % 3);

        uint32_t st = sb + (uint32_t)(ch % 3) * 32768u;
#pragma unroll
        for (int ks = 0; ks < 2; ks++) {
            uint32_t ah[4][4], al[4][4];
#pragma unroll
            for (int mf = 0; mf < 4; mf++) {
                int row = wm * 64 + mf * 16 + a_r;
                uint32_t off = SWZ64((uint32_t)(row * 64 + (ks * 2 + a_c) * 16));
                ldmx4(ah[mf], st + off);
                ldmx4(al[mf], st + 8192 + off);
            }
#pragma unroll
            for (int np = 0; np < 4; np++) {
                int row = wn * 64 + np * 16 + b_r;
                uint32_t off = SWZ64((uint32_t)(row * 64 + (ks * 2 + b_c) * 16));
                uint32_t bh4[4], bl4[4];
                ldmx4(bh4, st + 16384 + off);
                ldmx4(bl4, st + 24576 + off);
#pragma unroll
                for (int mf = 0; mf < 4; mf++) {
                    float* d0 = acc[mf][np * 2];
                    mma16816(d0, ah[mf], bh4);
                    mma16816(d0, ah[mf], bl4);
                    mma16816(d0, al[mf], bh4);
                    float* d1 = acc[mf][np * 2 + 1];
                    mma16816(d1, ah[mf], bh4 + 2);
                    mma16816(d1, ah[mf], bl4 + 2);
                    mma16816(d1, al[mf], bh4 + 2);
                }
            }
        }
        __syncthreads();
    }

    int g = lane >> 2, tg = lane & 3;
#pragma unroll
    for (int mf = 0; mf < 4; mf++)
#pragma unroll
        for (int nf = 0; nf < 8; nf++) {
            int rA = wm * 64 + mf * 16 + g;
            int cc = wn * 64 + nf * 8 + tg * 2;
            float* d = acc[mf][nf];
            if (C) {
                *(float2*)(C + coff + (size_t)rA * ldc + cc)       = make_float2(d[0], d[1]);
                *(float2*)(C + coff + (size_t)(rA + 8) * ldc + cc) = make_float2(d[2], d[3]);
            } else {
                st_hl(Chi, Clo, coff + (size_t)rA * ldc + cc,       d[0], d[1]);
                st_hl(Chi, Clo, coff + (size_t)(rA + 8) * ldc + cc, d[2], d[3]);
            }
        }
#undef ISSUE
}

// ---------------- fused flash attention ----------------
// Br=128 (8 warps x 16 rows), Bc=64. Q hi/lo resident (64KB), K/V hi/lo 2-stage.
// SMEM: [Qhi 0..32K][Qlo 32K..64K] stages at 64K + s*64K:
//   [Khi 0..16K][Klo 16K..32K][Vhi 32K..48K][Vlo 48K..64K]
__global__ void __launch_bounds__(256, 1) flash_kernel(
    const bf16* __restrict__ Qhi, const bf16* __restrict__ Qlo,
    const bf16* __restrict__ Khi, const bf16* __restrict__ Klo,
    const bf16* __restrict__ Vthi, const bf16* __restrict__ Vtlo,
    bf16* __restrict__ ctxh, bf16* __restrict__ ctxl)
{
    int qt = (int)gridDim.x - 1 - (int)blockIdx.x;   // big tiles first
    int h = blockIdx.y;
    int kv = h >> 2;
    int tid = threadIdx.x, lane = tid & 31, wid = tid >> 5;

    uint32_t sb = smem_u32(dsm);
    const uint32_t ST0 = 65536;

    // Q tile load (once): 2 x 32KB (4 subtiles [128][32] each)
    {
        size_t qg = (size_t)(qt * 128) * QDIM + (size_t)h * HD;
#pragma unroll
        for (int i = 0; i < 16; i++) {
            int id = tid + i * 256;
            int hl = id >> 11, rem = id & 2047;
            int row = rem >> 4, c = rem & 15;
            int kc = c >> 2, cc = c & 3;
            uint32_t dst = sb + (uint32_t)(hl * 32768 + kc * 8192) +
                           SWZ64((uint32_t)(row * 64 + cc * 16));
            const bf16* src = (hl ? Qlo : Qhi) + qg + (size_t)row * QDIM + kc * 32 + cc * 8;
            CP16(dst, src);
        }
        CP_COMMIT();
    }

#define KV_ISSUE(n, s) do {                                                     \
        uint32_t st_ = sb + ST0 + (uint32_t)(s) * 65536u;                       \
        int t0_ = (n) * 64;                                                     \
        _Pragma("unroll")                                                       \
        for (int i_ = 0; i_ < 8; i_++) {                                        \
            int id = tid + i_ * 256;                                            \
            int hl = id >> 10, rem = id & 1023;                                 \
            int row = rem >> 4, c = rem & 15;                                   \
            int kc = c >> 2, cc = c & 3;                                        \
            uint32_t dst = st_ + (uint32_t)(hl * 16384 + kc * 4096) +           \
                           SWZ64((uint32_t)(row * 64 + cc * 16));               \
            const bf16* src = (hl ? Klo : Khi) +                                \
                ((size_t)kv * SEQ + t0_ + row) * HD + kc * 32 + cc * 8;         \
            CP16(dst, src);                                                     \
        }                                                                       \
        _Pragma("unroll")                                                       \
        for (int i_ = 0; i_ < 8; i_++) {                                        \
            int id = tid + i_ * 256;                                            \
            int hl = id >> 10, rem = id & 1023;                                 \
            int row = rem >> 3, c = rem & 7;                                    \
            int tc = c >> 2, cc = c & 3;                                        \
            uint32_t dst = st_ + 32768u + (uint32_t)(hl * 16384 + tc * 8192) +  \
                           SWZ64((uint32_t)(row * 64 + cc * 16));               \
            const bf16* src = (hl ? Vtlo : Vthi) +                              \
                ((size_t)kv * HD + row) * SEQ + t0_ + tc * 32 + cc * 8;         \
            CP16(dst, src);                                                     \
        }                                                                       \
        CP_COMMIT();                                                            \
    } while (0)

    int nsteps = 2 * qt + 2;
    KV_ISSUE(0, 0);
    if (nsteps > 1) KV_ISSUE(1, 1);

    float o[16][4];
#pragma unroll
    for (int i = 0; i < 16; i++)
#pragma unroll
        for (int e = 0; e < 4; e++) o[i][e] = 0.f;
    float m0 = -1e30f, m1 = -1e30f, l0 = 0.f, l1 = 0.f;

    int a_r = lane & 15, a_c = lane >> 4;
    int b_q = lane >> 3, b_r = (b_q >> 1) * 8 + (lane & 7), b_c = b_q & 1;

    for (int n = 0; n < nsteps; n++) {
        if (n + 1 < nsteps) CP_WAIT1(); else CP_WAIT0();
        __syncthreads();
        uint32_t st = sb + ST0 + (uint32_t)(n & 1) * 65536u;

        // ---- S = Q K^T (bf16x3) ----
        float s[8][4];
#pragma unroll
        for (int i = 0; i < 8; i++)
#pragma unroll
            for (int e = 0; e < 4; e++) s[i][e] = 0.f;

#pragma unroll
        for (int kc = 0; kc < 4; kc++)
#pragma unroll
            for (int ks = 0; ks < 2; ks++) {
                uint32_t ah[4], al[4];
                {
                    int row = wid * 16 + a_r;
                    uint32_t off = (uint32_t)(kc * 8192) +
                                   SWZ64((uint32_t)(row * 64 + (ks * 2 + a_c) * 16));
                    ldmx4(ah, sb + off);
                    ldmx4(al, sb + 32768u + off);
                }
#pragma unroll
                for (int np = 0; np < 4; np++) {
                    int row = np * 16 + b_r;
                    uint32_t off = (uint32_t)(kc * 4096) +
                                   SWZ64((uint32_t)(row * 64 + (ks * 2 + b_c) * 16));
                    uint32_t bh4[4], bl4[4];
                    ldmx4(bh4, st + off);
                    ldmx4(bl4, st + 16384u + off);
                    float* d0 = s[np * 2];
                    mma16816(d0, ah, bh4);
                    mma16816(d0, ah, bl4);
                    mma16816(d0, al, bh4);
                    float* d1 = s[np * 2 + 1];
                    mma16816(d1, ah, bh4 + 2);
                    mma16816(d1, ah, bl4 + 2);
                    mma16816(d1, al, bh4 + 2);
                }
            }

        // ---- causal mask (diagonal tiles only) ----
        if (n >= nsteps - 2) {
            int row0 = qt * 128 + wid * 16 + (lane >> 2);
            int colb = n * 64 + (lane & 3) * 2;
#pragma unroll
            for (int nf = 0; nf < 8; nf++) {
                int c0 = colb + nf * 8;
                if (c0 > row0)         s[nf][0] = -1e30f;
                if (c0 + 1 > row0)     s[nf][1] = -1e30f;
                if (c0 > row0 + 8)     s[nf][2] = -1e30f;
                if (c0 + 1 > row0 + 8) s[nf][3] = -1e30f;
            }
        }

        // ---- online softmax ----
        float r0 = -1e30f, r1 = -1e30f;
#pragma unroll
        for (int nf = 0; nf < 8; nf++) {
            r0 = fmaxf(r0, fmaxf(s[nf][0], s[nf][1]));
            r1 = fmaxf(r1, fmaxf(s[nf][2], s[nf][3]));
        }
        r0 = fmaxf(r0, __shfl_xor_sync(0xffffffffu, r0, 1));
        r0 = fmaxf(r0, __shfl_xor_sync(0xffffffffu, r0, 2));
        r1 = fmaxf(r1, __shfl_xor_sync(0xffffffffu, r1, 1));
        r1 = fmaxf(r1, __shfl_xor_sync(0xffffffffu, r1, 2));
        float mn0 = fmaxf(m0, r0), mn1 = fmaxf(m1, r1);
        float al0 = __expf(m0 - mn0), al1 = __expf(m1 - mn1);
        m0 = mn0; m1 = mn1;
        float sm0 = 0.f, sm1 = 0.f;
#pragma unroll
        for (int nf = 0; nf < 8; nf++) {
            s[nf][0] = __expf(s[nf][0] - m0);
            s[nf][1] = __expf(s[nf][1] - m0);
            s[nf][2] = __expf(s[nf][2] - m1);
            s[nf][3] = __expf(s[nf][3] - m1);
            sm0 += s[nf][0] + s[nf][1];
            sm1 += s[nf][2] + s[nf][3];
        }
        sm0 += __shfl_xor_sync(0xffffffffu, sm0, 1);
        sm0 += __shfl_xor_sync(0xffffffffu, sm0, 2);
        sm1 += __shfl_xor_sync(0xffffffffu, sm1, 1);
        sm1 += __shfl_xor_sync(0xffffffffu, sm1, 2);
        l0 = l0 * al0 + sm0;
        l1 = l1 * al1 + sm1;
#pragma unroll
        for (int i = 0; i < 16; i++) {
            o[i][0] *= al0; o[i][1] *= al0;
            o[i][2] *= al1; o[i][3] *= al1;
        }

        // ---- O += P V (bf16x3: PhVh + PlVh + PhVl) ----
#pragma unroll
        for (int kb = 0; kb < 4; kb++) {
            uint32_t ph[4], pl[4];
            pack_hl(s[2 * kb][0],     s[2 * kb][1],     ph[0], pl[0]);
            pack_hl(s[2 * kb][2],     s[2 * kb][3],     ph[1], pl[1]);
            pack_hl(s[2 * kb + 1][0], s[2 * kb + 1][1], ph[2], pl[2]);
            pack_hl(s[2 * kb + 1][2], s[2 * kb + 1][3], ph[3], pl[3]);
            uint32_t vbase = 32768u + (uint32_t)((kb >> 1) * 8192);
            int kcol = ((kb & 1) * 2 + b_c) * 16;
#pragma unroll
            for (int nb = 0; nb < 8; nb++) {
                int row = nb * 16 + b_r;
                uint32_t off = vbase + SWZ64((uint32_t)(row * 64 + kcol));
                uint32_t vh4[4], vl4[4];
                ldmx4(vh4, st + off);
                ldmx4(vl4, st + 16384u + off);
                float* d0 = o[nb * 2];
                mma16816(d0, ph, vh4);
                mma16816(d0, pl, vh4);
                mma16816(d0, ph, vl4);
                float* d1 = o[nb * 2 + 1];
                mma16816(d1, ph, vh4 + 2);
                mma16816(d1, pl, vh4 + 2);
                mma16816(d1, ph, vl4 + 2);
            }
        }
        __syncthreads();
        if (n + 2 < nsteps) KV_ISSUE(n + 2, n & 1);
    }

    // ---- epilogue: O /= l -> ctx hi/lo ----
    float inv0 = 1.f / l0, inv1 = 1.f / l1;
    int row0 = qt * 128 + wid * 16 + (lane >> 2);
    size_t base = (size_t)row0 * QDIM + (size_t)h * HD;
#pragma unroll
    for (int nf = 0; nf < 16; nf++) {
        int col = nf * 8 + (lane & 3) * 2;
        st_hl(ctxh, ctxl, base + col,             o[nf][0] * inv0, o[nf][1] * inv0);
        st_hl(ctxh, ctxl, base + 8 * QDIM + col,  o[nf][2] * inv1, o[nf][3] * inv1);
    }
#undef KV_ISSUE
}

// ---------------- converters ----------------
__global__ void convert_x_kernel(const float* __restrict__ x, bf16* __restrict__ hi,
                                 bf16* __restrict__ lo)
{
    size_t i = (size_t)blockIdx.x * blockDim.x + threadIdx.x;
    float4 v = ((const float4*)x)[i];
    bf162 h01 = __floats2bfloat162_rn(v.x, v.y);
    bf162 h23 = __floats2bfloat162_rn(v.z, v.w);
    float2 f01 = __bfloat1622float2(h01);
    float2 f23 = __bfloat1622float2(h23);
    ((bf162*)hi)[2 * i]     = h01;
    ((bf162*)hi)[2 * i + 1] = h23;
    ((bf162*)lo)[2 * i]     = __floats2bfloat162_rn(v.x - f01.x, v.y - f01.y);
    ((bf162*)lo)[2 * i + 1] = __floats2bfloat162_rn(v.z - f23.x, v.w - f23.y);
}

// W [K][N] fp32 -> Wt [N][K] hi/lo bf16
__global__ void convert_w_kernel(const float* __restrict__ W, bf16* __restrict__ hi,
                                 bf16* __restrict__ lo, int Kd, int Nd)
{
    __shared__ float tile[32][33];
    int n0 = blockIdx.x * 32, k0 = blockIdx.y * 32;
    int tx = threadIdx.x, ty = threadIdx.y;
#pragma unroll
    for (int j = 0; j < 32; j += 8)
        tile[ty + j][tx] = W[(size_t)(k0 + ty + j) * Nd + n0 + tx];
    __syncthreads();
#pragma unroll
    for (int j = 0; j < 32; j += 8) {
        int n = n0 + ty + j, k = k0 + tx;
        float v = tile[tx][ty + j];
        bf16 h = __float2bfloat16_rn(v);
        size_t off = (size_t)n * Kd + k;
        hi[off] = h;
        lo[off] = __float2bfloat16_rn(v - __bfloat162float(h));
    }
}

// ---------------- RMSNorm + RoPE -> bf16 hi/lo (+ optional fp32) ----------------
__global__ void norm_rope_kernel(
    const float* __restrict__ in, float* __restrict__ outf,
    bf16* __restrict__ outh, bf16* __restrict__ outl,
    const float* __restrict__ scale,
    const float* __restrict__ cosb, const float* __restrict__ sinb,
    int in_ts, int in_hs, int out_ts, int out_hs, float premul)
{
    int t = blockIdx.x, h = blockIdx.y, d = threadIdx.x;
    __shared__ float red[HD];
    __shared__ float sm[HD];

    float val = in[(size_t)t * in_ts + (size_t)h * in_hs + d];
    red[d] = val * val;
    __syncthreads();
#pragma unroll
    for (int s = 64; s > 0; s >>= 1) {
        if (d < s) red[d] += red[d + s];
        __syncthreads();
    }
    float rms = rsqrtf(red[0] * (1.0f / HD) + 1e-6f);
    float nv = val * rms * scale[d];
    sm[d] = nv;
    __syncthreads();
    float partner = (d < 64) ? sm[d + 64] : sm[d - 64];
    float rot = (d < 64) ? -partner : partner;
    float o = nv * cosb[t * HD + d] + rot * sinb[t * HD + d];

    size_t off = (size_t)t * out_ts + (size_t)h * out_hs + d;
    if (outf) outf[off] = o;
    float os = o * premul;
    bf16 hh = __float2bfloat16_rn(os);
    outh[off] = hh;
    outl[off] = __float2bfloat16_rn(os - __bfloat162float(hh));
}

// V: [t][kv*128+d] fp32 -> Vout fp32 [kv][t][d] + Vt hi/lo [kv][d][t]
__global__ void vtrans_kernel(const float* __restrict__ Vp, float* __restrict__ Vout,
                              bf16* __restrict__ Vthi, bf16* __restrict__ Vtlo)
{
    __shared__ float tile[32][33];
    int kv = blockIdx.z;
    int t0 = blockIdx.x * 32, d0 = blockIdx.y * 32;
    int tx = threadIdx.x, ty = threadIdx.y;
#pragma unroll
    for (int j = 0; j < 32; j += 8) {
        int t = t0 + ty + j;
        float v = Vp[(size_t)t * KVDIM + kv * HD + d0 + tx];
        tile[ty + j][tx] = v;
        Vout[((size_t)kv * SEQ + t) * HD + d0 + tx] = v;
    }
    __syncthreads();
#pragma unroll
    for (int j = 0; j < 32; j += 8) {
        int d = d0 + ty + j, t = t0 + tx;
        float v = tile[tx][ty + j];
        size_t off = ((size_t)kv * HD + d) * SEQ + t;
        bf16 h = __float2bfloat16_rn(v);
        Vthi[off] = h;
        Vtlo[off] = __float2bfloat16_rn(v - __bfloat162float(h));
    }
}

// ---------------- launch ----------------
extern "C" void kernel_launch(void* const* d_in, const int* in_sizes, int n_in,
                              void* d_out, int out_size)
{
    const float* x       = (const float*)d_in[0];
    const float* Wq      = (const float*)d_in[1];
    const float* Wk      = (const float*)d_in[2];
    const float* Wv      = (const float*)d_in[3];
    const float* Wo      = (const float*)d_in[4];
    const float* q_scale = (const float*)d_in[5];
    const float* k_scale = (const float*)d_in[6];
    const float* cosb    = (const float*)d_in[7];
    const float* sinb    = (const float*)d_in[8];

    float* out  = (float*)d_out;
    float* Kout = out  + (size_t)SEQ * DIN;
    float* Vout = Kout + (size_t)NKV * SEQ * HD;

    bf16 *xhi, *xlo, *Wqh, *Wql, *Wkh, *Wkl, *Wvh, *Wvl, *Woh, *Wol;
    bf16 *Qhi, *Qlo, *Khi, *Klo, *Vthi, *Vtlo, *ctxh, *ctxl;
    float *Qp, *Kp, *Vp;
    cudaGetSymbolAddress((void**)&xhi, g_xhi);   cudaGetSymbolAddress((void**)&xlo, g_xlo);
    cudaGetSymbolAddress((void**)&Wqh, g_Wqh);   cudaGetSymbolAddress((void**)&Wql, g_Wql);
    cudaGetSymbolAddress((void**)&Wkh, g_Wkh);   cudaGetSymbolAddress((void**)&Wkl, g_Wkl);
    cudaGetSymbolAddress((void**)&Wvh, g_Wvh);   cudaGetSymbolAddress((void**)&Wvl, g_Wvl);
    cudaGetSymbolAddress((void**)&Woh, g_Woh);   cudaGetSymbolAddress((void**)&Wol, g_Wol);
    cudaGetSymbolAddress((void**)&Qp, g_Qp);     cudaGetSymbolAddress((void**)&Kp, g_Kp);
    cudaGetSymbolAddress((void**)&Vp, g_Vp);
    cudaGetSymbolAddress((void**)&Qhi, g_Qhi);   cudaGetSymbolAddress((void**)&Qlo, g_Qlo);
    cudaGetSymbolAddress((void**)&Khi, g_Khi);   cudaGetSymbolAddress((void**)&Klo, g_Klo);
    cudaGetSymbolAddress((void**)&Vthi, g_Vthi); cudaGetSymbolAddress((void**)&Vtlo, g_Vtlo);
    cudaGetSymbolAddress((void**)&ctxh, g_ctxh); cudaGetSymbolAddress((void**)&ctxl, g_ctxl);

    const int SMEM = 3 * 32768;       // gemm
    const int FSMEM = 65536 + 2 * 65536;  // flash: 196608
    cudaFuncSetAttribute(gemm_bf3, cudaFuncAttributeMaxDynamicSharedMemorySize, SMEM);
    cudaFuncSetAttribute(flash_kernel, cudaFuncAttributeMaxDynamicSharedMemorySize, FSMEM);

    dim3 blk(128);
    dim3 tblk(32, 8);

    // input conversions
    convert_x_kernel<<<(SEQ * DIN / 4) / 256, 256>>>(x, xhi, xlo);
    convert_w_kernel<<<dim3(QDIM / 32,  DIN / 32),  tblk>>>(Wq, Wqh, Wql, DIN, QDIM);
    convert_w_kernel<<<dim3(KVDIM / 32, DIN / 32),  tblk>>>(Wk, Wkh, Wkl, DIN, KVDIM);
    convert_w_kernel<<<dim3(KVDIM / 32, DIN / 32),  tblk>>>(Wv, Wvh, Wvl, DIN, KVDIM);
    convert_w_kernel<<<dim3(DIN / 32,   QDIM / 32), tblk>>>(Wo, Woh, Wol, QDIM, DIN);

    // projections (C fp32)
    gemm_bf3<<<dim3(QDIM / BN,  SEQ / BM), blk, SMEM>>>(
        xhi, xlo, Wqh, Wql, Qp, nullptr, nullptr, DIN, DIN, QDIM, DIN);
    gemm_bf3<<<dim3(KVDIM / BN, SEQ / BM), blk, SMEM>>>(
        xhi, xlo, Wkh, Wkl, Kp, nullptr, nullptr, DIN, DIN, KVDIM, DIN);
    gemm_bf3<<<dim3(KVDIM / BN, SEQ / BM), blk, SMEM>>>(
        xhi, xlo, Wvh, Wvl, Vp, nullptr, nullptr, DIN, DIN, KVDIM, DIN);

    // norm+rope: Q gets 1/sqrt(HD) folded into hi/lo; K -> fp32 Kout + hi/lo [kv][t][d]
    const float scl = 0.08838834764831845f;
    norm_rope_kernel<<<dim3(SEQ, NH),  HD>>>(Qp, nullptr, Qhi, Qlo, q_scale, cosb, sinb,
                                             QDIM, HD, QDIM, HD, scl);
    norm_rope_kernel<<<dim3(SEQ, NKV), HD>>>(Kp, Kout, Khi, Klo, k_scale, cosb, sinb,
                                             KVDIM, HD, HD, SEQ * HD, 1.0f);
    vtrans_kernel<<<dim3(SEQ / 32, HD / 32, NKV), tblk>>>(Vp, Vout, Vthi, Vtlo);

    // fused attention: scores + softmax + PV -> ctx hi/lo
    flash_kernel<<<dim3(16, NH), 256, FSMEM>>>(Qhi, Qlo, Khi, Klo, Vthi, Vtlo, ctxh, ctxl);

    // out projection
    gemm_bf3<<<dim3(DIN / BN, SEQ / BM), blk, SMEM>>>(
        ctxh, ctxl, Woh, Wol, out, nullptr, nullptr, QDIM, QDIM, DIN, QDIM);
}